// round 1
// baseline (speedup 1.0000x reference)
#include <cuda_runtime.h>
#include <cuda_bf16.h>

// Problem shape constants (fixed by setup_inputs)
#define B_  2
#define HI  64
#define WI  64
#define DI  32
#define CC  16
#define FF  8
#define HO  128
#define WO  128
#define DO_ 64

// Block: 256 threads = 8 warps. Warp w handles (wo = blockIdx.x*4 + w/2, parity = w&1),
// lane l handles do = 2*l + parity. Grid: (WO/4, HO, B).
__global__ __launch_bounds__(256, 8)
void sparse_conv3d_transpose_kernel(const float* __restrict__ images,
                                    const int*   __restrict__ base_plane,
                                    const float* __restrict__ kernel,
                                    const float* __restrict__ defv,
                                    float*       __restrict__ out)
{
    __shared__ float sw[27 * FF * CC];   // 13824 B: kernel[kh][kw][kd][f][c]
    for (int i = threadIdx.x; i < 27 * FF * CC; i += 256) sw[i] = kernel[i];
    __syncthreads();

    const int b    = blockIdx.z;
    const int ho   = blockIdx.y;
    const int warp = threadIdx.x >> 5;
    const int lane = threadIdx.x & 31;
    const int wo   = (blockIdx.x << 2) + (warp >> 1);
    const int par  = warp & 1;
    const int dout = (lane << 1) + par;

    const float dv  = *defv;
    const int   bpv = base_plane[(b * HO + ho) * WO + wo];

    float acc[FF];
    #pragma unroll
    for (int f = 0; f < FF; f++) acc[f] = 0.0f;

    #pragma unroll
    for (int kh = 0; kh < 3; kh++) {
        const int hn = ho + 1 - kh;
        if ((hn & 1) || hn < 0 || hn >= 2 * HI) continue;   // warp-uniform
        const int hi = hn >> 1;
        #pragma unroll
        for (int kw = 0; kw < 3; kw++) {
            const int wn = wo + 1 - kw;
            if ((wn & 1) || wn < 0 || wn >= 2 * WI) continue;  // warp-uniform
            const int wi = wn >> 1;
            // input-slab base depth at this input pixel
            const int bpg = base_plane[(b * HO + (hi << 1)) * WO + (wi << 1)] >> 1;
            const float4* __restrict__ irow =
                (const float4*)(images + ((size_t)((b * HI + hi) * WI + wi) * DI) * CC);
            #pragma unroll
            for (int kd = 0; kd < 3; kd++) {
                const int dn = bpv + dout + 1 - kd;
                if (dn & 1) continue;                      // warp-uniform (parity of bpv+par+1-kd)
                const int di = (dn >> 1) - bpg;            // = dbase + lane - bpg
                float4 v0, v1, v2, v3;
                if (di >= 0 && di < DI) {
                    const float4* p = irow + di * (CC / 4);
                    v0 = p[0]; v1 = p[1]; v2 = p[2]; v3 = p[3];
                } else {
                    v0 = make_float4(dv, dv, dv, dv);
                    v1 = v0; v2 = v0; v3 = v0;
                }
                const float4* __restrict__ w =
                    (const float4*)(sw + ((kh * 3 + kw) * 3 + kd) * FF * CC);
                #pragma unroll
                for (int f = 0; f < FF; f++) {
                    const float4 w0 = w[f * 4 + 0];
                    const float4 w1 = w[f * 4 + 1];
                    const float4 w2 = w[f * 4 + 2];
                    const float4 w3 = w[f * 4 + 3];
                    acc[f] += v0.x * w0.x + v0.y * w0.y + v0.z * w0.z + v0.w * w0.w
                            + v1.x * w1.x + v1.y * w1.y + v1.z * w1.z + v1.w * w1.w
                            + v2.x * w2.x + v2.y * w2.y + v2.z * w2.z + v2.w * w2.w
                            + v3.x * w3.x + v3.y * w3.y + v3.z * w3.z + v3.w * w3.w;
                }
            }
        }
    }

    float4* op = (float4*)(out + (((size_t)((b * HO + ho) * WO + wo) * DO_ + dout) * FF));
    op[0] = make_float4(acc[0], acc[1], acc[2], acc[3]);
    op[1] = make_float4(acc[4], acc[5], acc[6], acc[7]);
}

extern "C" void kernel_launch(void* const* d_in, const int* in_sizes, int n_in,
                              void* d_out, int out_size)
{
    const float* images     = (const float*)d_in[0];   // [2,64,64,32,16] f32
    const int*   base_plane = (const int*)  d_in[1];   // [2,128,128,1] i32
    const float* kern       = (const float*)d_in[2];   // [3,3,3,8,16] f32
    const float* defv       = (const float*)d_in[3];   // scalar f32 (zero)
    float*       out        = (float*)d_out;           // [2,128,128,64,8] f32

    dim3 grid(WO / 4, HO, B_);
    sparse_conv3d_transpose_kernel<<<grid, 256>>>(images, base_plane, kern, defv, out);
}

// round 5
// speedup vs baseline: 1.3244x; 1.3244x over previous
#include <cuda_runtime.h>
#include <cuda_bf16.h>

// Problem shape constants (fixed by setup_inputs)
#define B_  2
#define HI  64
#define WI  64
#define DI  32
#define CC  16
#define FF  8
#define HO  128
#define WO  128
#define DO_ 64

// ---- packed f32x2 helpers (sm_100+; ptxas never emits these from C++) ----
__device__ __forceinline__ unsigned long long fma2(unsigned long long a,
                                                   unsigned long long b,
                                                   unsigned long long c) {
    unsigned long long d;
    asm("fma.rn.f32x2 %0, %1, %2, %3;" : "=l"(d) : "l"(a), "l"(b), "l"(c));
    return d;
}
__device__ __forceinline__ void ldg128(unsigned long long& a, unsigned long long& b,
                                       const float* p) {
    asm("ld.global.nc.v2.b64 {%0, %1}, [%2];" : "=l"(a), "=l"(b) : "l"(p));
}
__device__ __forceinline__ void lds128(unsigned long long& a, unsigned long long& b,
                                       unsigned addr) {
    asm("ld.shared.v2.b64 {%0, %1}, [%2];" : "=l"(a), "=l"(b) : "r"(addr));
}
__device__ __forceinline__ unsigned long long pack2(float x) {
    unsigned long long d;
    asm("mov.b64 %0, {%1, %1};" : "=l"(d) : "f"(x));
    return d;
}
__device__ __forceinline__ float lo32(unsigned long long a) {
    return __uint_as_float((unsigned)a);
}
__device__ __forceinline__ float hi32(unsigned long long a) {
    return __uint_as_float((unsigned)(a >> 32));
}

// Block: 256 threads = 8 warps. Warp w: wo = blockIdx.x*4 + w/2, parity = w&1.
// Lane l: dout = 2*l + parity (so per warp-uniform kd-tap, di = lane + const).
__global__ __launch_bounds__(256)
void sparse_conv3d_transpose_kernel(const float* __restrict__ images,
                                    const int*   __restrict__ base_plane,
                                    const float* __restrict__ kernel,
                                    const float* __restrict__ defv,
                                    float*       __restrict__ out)
{
    __shared__ __align__(16) float sw[27 * FF * CC];   // 13824 B
    for (int i = threadIdx.x; i < 27 * FF * CC; i += 256) sw[i] = kernel[i];
    __syncthreads();

    const int b    = blockIdx.z;
    const int ho   = blockIdx.y;
    const int warp = threadIdx.x >> 5;
    const int lane = threadIdx.x & 31;
    const int wo   = (blockIdx.x << 2) + (warp >> 1);
    const int par  = warp & 1;
    const int dout = (lane << 1) + par;

    const float dv = *defv;
    const unsigned long long dv2 = pack2(dv);
    const int bpv = __ldg(base_plane + (b * HO + ho) * WO + wo);

    const unsigned swbase = (unsigned)__cvta_generic_to_shared(sw);

    unsigned long long acc[FF];    // each holds a (c-even, c-odd) partial pair
    #pragma unroll
    for (int f = 0; f < FF; f++) acc[f] = 0ull;

    #pragma unroll
    for (int kh = 0; kh < 3; kh++) {
        const int hn = ho + 1 - kh;           // hn == -1 is odd -> caught by &1
        if ((hn & 1) || hn >= 2 * HI) continue;   // warp-uniform
        const int hi = hn >> 1;
        #pragma unroll
        for (int kw = 0; kw < 3; kw++) {
            const int wn = wo + 1 - kw;
            if ((wn & 1) || wn >= 2 * WI) continue;  // warp-uniform
            const int wi = wn >> 1;
            const int bpg = __ldg(base_plane + (b * HO + (hi << 1)) * WO + (wi << 1)) >> 1;
            const float* __restrict__ irow =
                images + (size_t)(((b * HI + hi) * WI + wi) * DI) * CC;
            #pragma unroll
            for (int kd = 0; kd < 3; kd++) {
                const int dn0 = bpv + par + 1 - kd;
                if (dn0 & 1) continue;                 // warp-uniform parity tap
                const int di = (dn0 >> 1) + lane - bpg;
                unsigned long long v[8];
                if (di >= 0 && di < DI) {
                    const float* p = irow + di * CC;
                    ldg128(v[0], v[1], p);
                    ldg128(v[2], v[3], p + 4);
                    ldg128(v[4], v[5], p + 8);
                    ldg128(v[6], v[7], p + 12);
                } else {
                    #pragma unroll
                    for (int j = 0; j < 8; j++) v[j] = dv2;
                }
                const unsigned wb = swbase +
                    (unsigned)(((kh * 3 + kw) * 3 + kd) * FF * CC * 4);
                #pragma unroll
                for (int f = 0; f < FF; f++) {
                    unsigned long long w0, w1, w2, w3, w4, w5, w6, w7;
                    lds128(w0, w1, wb + f * 64);
                    lds128(w2, w3, wb + f * 64 + 16);
                    lds128(w4, w5, wb + f * 64 + 32);
                    lds128(w6, w7, wb + f * 64 + 48);
                    acc[f] = fma2(v[0], w0, acc[f]);
                    acc[f] = fma2(v[1], w1, acc[f]);
                    acc[f] = fma2(v[2], w2, acc[f]);
                    acc[f] = fma2(v[3], w3, acc[f]);
                    acc[f] = fma2(v[4], w4, acc[f]);
                    acc[f] = fma2(v[5], w5, acc[f]);
                    acc[f] = fma2(v[6], w6, acc[f]);
                    acc[f] = fma2(v[7], w7, acc[f]);
                }
            }
        }
    }

    // horizontal reduce the packed halves and store
    float r[FF];
    #pragma unroll
    for (int f = 0; f < FF; f++) r[f] = lo32(acc[f]) + hi32(acc[f]);

    float4* op = (float4*)(out + (((size_t)((b * HO + ho) * WO + wo) * DO_ + dout) * FF));
    op[0] = make_float4(r[0], r[1], r[2], r[3]);
    op[1] = make_float4(r[4], r[5], r[6], r[7]);
}

extern "C" void kernel_launch(void* const* d_in, const int* in_sizes, int n_in,
                              void* d_out, int out_size)
{
    const float* images     = (const float*)d_in[0];   // [2,64,64,32,16] f32
    const int*   base_plane = (const int*)  d_in[1];   // [2,128,128,1] i32
    const float* kern       = (const float*)d_in[2];   // [3,3,3,8,16] f32
    const float* defv       = (const float*)d_in[3];   // scalar f32 (zero)
    float*       out        = (float*)d_out;           // [2,128,128,64,8] f32

    dim3 grid(WO / 4, HO, B_);
    sparse_conv3d_transpose_kernel<<<grid, 256>>>(images, base_plane, kern, defv, out);
}